// round 12
// baseline (speedup 1.0000x reference)
#include <cuda_runtime.h>
#include <mma.h>
#include <cstdint>

using namespace nvcuda;

// ---------------------------------------------------------------------------
// Problem constants
// ---------------------------------------------------------------------------
#define HDIM    128
#define MSGDIM  256
#define GDIM    384

// ---------------------------------------------------------------------------
// Shared-memory layout (float offsets)
//   A tiles : [2][64][LDA]      (messages / gathered h rows, K-chunk = 32)
//   W tiles : [2][512][LDA]     (weight rows == output gate columns)
//   after the main loop the A/W region is reused as the 64 x 516 gate dump
// ---------------------------------------------------------------------------
#define LDA 36
#define DLD 516
static constexpr int OFF_A    = 0;                      // 2*64*36   = 4608
static constexpr int OFF_W    = 4608;                   // 2*512*36  = 36864
static constexpr int OFF_NODE = 41472;                  // 64 ints
static constexpr int OFF_TS   = 41536;                  // 64 f32
static constexpr int OFF_BIH  = 41600;                  // 384 f32
static constexpr int OFF_BHH  = 41984;                  // 384 f32
static constexpr int SMEM_FLOATS = 42368;
static constexpr int SMEM_BYTES  = SMEM_FLOATS * 4;     // 169472 B

// ---------------------------------------------------------------------------
// Pass-through copy (float4 grid-stride)
// ---------------------------------------------------------------------------
__global__ void copy_f4(const float4* __restrict__ src, float4* __restrict__ dst,
                        size_t n4) {
    size_t i = (size_t)blockIdx.x * blockDim.x + threadIdx.x;
    size_t stride = (size_t)gridDim.x * blockDim.x;
    for (; i < n4; i += stride) dst[i] = src[i];
}

__device__ __forceinline__ void cpa16(float* smem_dst, const float* gsrc) {
    uint32_t d = (uint32_t)__cvta_generic_to_shared(smem_dst);
    asm volatile("cp.async.cg.shared.global [%0], [%1], 16;" :: "r"(d), "l"(gsrc));
}

// ---------------------------------------------------------------------------
// Fully fused GRU memory update (wmma tf32):
//   gate cols 0..255  = r,z  : accumulated over BOTH matmuls (warps wn 0..3)
//   gate cols 256..383 = i_n : messages @ W_ih only          (warps wn 4,5)
//   gate cols 384..511 = h_n : gathered h @ W_hh n-rows only (warps wn 6,7)
// CTA: 64 batch rows, 512 threads (16 warps, warp tile 32 x 64).
// K pipeline: chunks 0..7 (K=256, messages/W_ih), 8..11 (K=128, h/W_hh).
// ---------------------------------------------------------------------------
__global__ void __launch_bounds__(512, 1)
gru_fused(const float* __restrict__ memory,
          const int*   __restrict__ ids,
          const float* __restrict__ messages,
          const float* __restrict__ ts,
          const float* __restrict__ W_ih,
          const float* __restrict__ W_hh,
          const float* __restrict__ b_ih,
          const float* __restrict__ b_hh,
          float* __restrict__ out_mem,
          float* __restrict__ out_lu,
          int B) {
    extern __shared__ float sm[];
    const int t  = threadIdx.x;
    const int rb = blockIdx.x * 64;

    // ---- prologue: node ids, timestamps, biases
    if (t < 64) {
        int r = rb + t; if (r > B - 1) r = B - 1;
        ((int*)(sm + OFF_NODE))[t] = ids[r];
        sm[OFF_TS + t] = ts[r];
    }
    if (t < GDIM) {
        sm[OFF_BIH + t] = b_ih[t];
        sm[OFF_BHH + t] = b_hh[t];
    }
    __syncthreads();
    const int* s_node = (const int*)(sm + OFF_NODE);

    // ---- warp tiling
    const int wid = t >> 5;
    const int wm  = wid >> 3;      // 0..1  -> rows wm*32
    const int wn  = wid & 7;       // 0..7  -> cols wn*64

    wmma::fragment<wmma::accumulator, 16, 16, 8, float> acc[2][4];
    #pragma unroll
    for (int mf = 0; mf < 2; mf++)
        #pragma unroll
        for (int nf = 0; nf < 4; nf++)
            wmma::fill_fragment(acc[mf][nf], 0.0f);

    // ---- async stage loader: chunk i -> buffer i&1
    auto load_stage = [&](int i) {
        const int buf = i & 1;
        float* As = sm + OFF_A + buf * 64 * LDA;
        float* Ws = sm + OFF_W + buf * 512 * LDA;
        const int row = t >> 3, c4 = (t & 7) * 4;
        if (i < 8) {                            // phase A: messages / W_ih
            const int k0 = i * 32;
            int rg = rb + row; if (rg > B - 1) rg = B - 1;
            cpa16(As + row * LDA + c4, messages + (size_t)rg * MSGDIM + k0 + c4);
            #pragma unroll
            for (int u = 0; u < 8; u++) {
                int fi = u * 512 + t, wr = fi >> 3, wc = (fi & 7) * 4;
                int wsrc = (wr < GDIM) ? wr : wr - 128;      // rows 384..511 dup
                cpa16(Ws + wr * LDA + wc, W_ih + (size_t)wsrc * MSGDIM + k0 + wc);
            }
        } else {                                // phase B: gathered h / W_hh
            const int k0 = (i - 8) * 32;
            int node = s_node[row];
            cpa16(As + row * LDA + c4, memory + (size_t)node * HDIM + k0 + c4);
            #pragma unroll
            for (int u = 0; u < 8; u++) {
                int fi = u * 512 + t, wr = fi >> 3, wc = (fi & 7) * 4;
                // smem row r: r<256 -> W_hh row r (r,z); r>=384 -> W_hh row r-128 (n)
                int wsrc = (wr < 256) ? wr : wr - 128;
                cpa16(Ws + wr * LDA + wc, W_hh + (size_t)wsrc * HDIM + k0 + wc);
            }
        }
        asm volatile("cp.async.commit_group;");
    };

    // ---- main pipeline: 12 chunks of K=32
    load_stage(0);
    for (int i = 0; i < 12; i++) {
        if (i < 11) {
            load_stage(i + 1);
            asm volatile("cp.async.wait_group 1;");
        } else {
            asm volatile("cp.async.wait_group 0;");
        }
        __syncthreads();

        // gate which warp-columns participate in this phase
        const bool active = (i < 8) ? (wn < 6) : (wn < 4 || wn >= 6);
        if (active) {
            const int buf = i & 1;
            const float* Ab = sm + OFF_A + buf * 64 * LDA + (wm * 32) * LDA;
            const float* Wb = sm + OFF_W + buf * 512 * LDA + (wn * 64) * LDA;
            #pragma unroll
            for (int ks = 0; ks < 4; ks++) {
                wmma::fragment<wmma::matrix_a, 16, 16, 8,
                               wmma::precision::tf32, wmma::row_major> af[2];
                wmma::fragment<wmma::matrix_b, 16, 16, 8,
                               wmma::precision::tf32, wmma::col_major> bf[4];
                #pragma unroll
                for (int mf = 0; mf < 2; mf++)
                    wmma::load_matrix_sync(af[mf], Ab + mf * 16 * LDA + ks * 8, LDA);
                #pragma unroll
                for (int nf = 0; nf < 4; nf++)
                    wmma::load_matrix_sync(bf[nf], Wb + nf * 16 * LDA + ks * 8, LDA);
                #pragma unroll
                for (int mf = 0; mf < 2; mf++)
                    #pragma unroll
                    for (int nf = 0; nf < 4; nf++)
                        wmma::mma_sync(acc[mf][nf], af[mf], bf[nf], acc[mf][nf]);
            }
        }
        __syncthreads();
    }

    // ---- dump accumulators to smem (reuse A/W region): 64 x 516
    float* dump = sm;
    #pragma unroll
    for (int mf = 0; mf < 2; mf++)
        #pragma unroll
        for (int nf = 0; nf < 4; nf++)
            wmma::store_matrix_sync(dump + (wm * 32 + mf * 16) * DLD + wn * 64 + nf * 16,
                                    acc[mf][nf], DLD, wmma::mem_row_major);
    __syncthreads();

    // ---- GRU epilogue + scatter: 64 rows x 128 h = 8192 elems, 16 per thread
    const float* bih = sm + OFF_BIH;
    const float* bhh = sm + OFF_BHH;
    #pragma unroll
    for (int e = 0; e < 16; e++) {
        int idx = e * 512 + t;
        int m = idx >> 7, h = idx & 127;
        int brow = rb + m;
        int node = s_node[m];
        float rg = dump[m * DLD + h]       + bih[h]       + bhh[h];
        float zg = dump[m * DLD + 128 + h] + bih[128 + h] + bhh[128 + h];
        float ig = dump[m * DLD + 256 + h] + bih[256 + h];
        float hg = dump[m * DLD + 384 + h] + bhh[256 + h];
        float r = 1.0f / (1.0f + expf(-rg));
        float z = 1.0f / (1.0f + expf(-zg));
        float n = tanhf(ig + r * hg);
        float hp = memory[(size_t)node * HDIM + h];
        if (brow < B)
            out_mem[(size_t)node * HDIM + h] = (1.0f - z) * n + z * hp;
    }
    if (t < 64 && rb + t < B)
        out_lu[s_node[t]] = sm[OFF_TS + t];
}

// ---------------------------------------------------------------------------
// kernel_launch
// Inputs: 0 memory 1 last_update 2 ids 3 messages 4 ts 5 W_ih 6 W_hh 7 b_ih 8 b_hh
// Output: [memory' | last_update'] f32
// ---------------------------------------------------------------------------
extern "C" void kernel_launch(void* const* d_in, const int* in_sizes, int n_in,
                              void* d_out, int out_size) {
    const float* memory      = (const float*)d_in[0];
    const float* last_update = (const float*)d_in[1];
    const int*   ids         = (const int*)d_in[2];
    const float* messages    = (const float*)d_in[3];
    const float* ts          = (const float*)d_in[4];
    const float* W_ih        = (const float*)d_in[5];
    const float* W_hh        = (const float*)d_in[6];
    const float* b_ih        = (const float*)d_in[7];
    const float* b_hh        = (const float*)d_in[8];

    const int    B      = in_sizes[2];
    const size_t memN   = (size_t)in_sizes[0];
    const size_t nNodes = (size_t)in_sizes[1];

    float* out_mem = (float*)d_out;
    float* out_lu  = (float*)d_out + memN;

    cudaFuncSetAttribute(gru_fused,
                         cudaFuncAttributeMaxDynamicSharedMemorySize, SMEM_BYTES);

    // Phase 0: pass-through copies (updated rows overwritten by the fused kernel)
    copy_f4<<<2960, 256>>>((const float4*)memory, (float4*)out_mem, memN / 4);
    copy_f4<<<256, 256>>>((const float4*)last_update, (float4*)out_lu, nNodes / 4);

    // Phase 1: fused GEMM(+GEMM) + GRU epilogue + scatter
    int grid = (B + 63) / 64;
    gru_fused<<<grid, 512, SMEM_BYTES>>>(memory, ids, messages, ts,
                                         W_ih, W_hh, b_ih, b_hh,
                                         out_mem, out_lu, B);
}